// round 9
// baseline (speedup 1.0000x reference)
#include <cuda_runtime.h>
#include <cuda_fp16.h>

// Problem constants (fixed by setup_inputs): N=50000, E=800000, F=64, U=64, H=8
#define Fd   64
#define Hh   8
#define HU   512          // H * U
#define NMAX 50000
#define EMAX 800000
#define CHUNK 64          // edges per warp in k_edge

// ---------------- static scratch (no allocations allowed) ----------------
__device__ __align__(16) __half d_g[(size_t)NMAX * HU];   // g fp16 (~51 MB)
__device__ __align__(16) uint2  d_x16[(size_t)NMAX * 16]; // X in fp16 (4 halves per uint2)
__device__ __align__(16) uint2  d_Cfrag[4 * 64 * 32];     // B fragments, 64 KB (kt, nt, lane)
__device__ float d_asrc[NMAX * Hh];
__device__ float d_adst[NMAX * Hh];
__device__ __align__(16) float d_asum[NMAX * Hh];         // per (src,h) attention sums
__device__ __align__(16) float d_oacc[(size_t)NMAX * Fd]; // pre-leaky output accumulator
__device__ float d_wa[2 * Hh * Fd];                       // folded attention vectors

__device__ __forceinline__ float leaky(float v) { return v >= 0.f ? v : 0.2f * v; }

__device__ __forceinline__ void mma16816(float* c, unsigned a0, unsigned a1,
                                         unsigned a2, unsigned a3,
                                         unsigned b0, unsigned b1) {
    asm volatile(
        "mma.sync.aligned.m16n8k16.row.col.f32.f16.f16.f32 "
        "{%0,%1,%2,%3}, {%4,%5,%6,%7}, {%8,%9}, {%0,%1,%2,%3};\n"
        : "+f"(c[0]), "+f"(c[1]), "+f"(c[2]), "+f"(c[3])
        : "r"(a0), "r"(a1), "r"(a2), "r"(a3), "r"(b0), "r"(b1));
}

// ---------------- K0: fold weights into B-fragments + wa; zero accumulators --------
// C[f][n] = sum_u W[h][f][u] * M[(h*64+u)*64 + j]  (h = n>>6, j = n&63), stored as
// fp16 mma B-fragments: frag(kt,nt,lane) = {C[k0][n],C[k0+1][n] | C[k0+8][n],C[k0+9][n]}
// with k0 = kt*16 + (lane&3)*2, n = nt*8 + (lane>>2).
__global__ void k_prep(const float* __restrict__ W, const float* __restrict__ a,
                       const float* __restrict__ M, int N) {
    int idx = blockIdx.x * blockDim.x + threadIdx.x;
    int nthr = gridDim.x * blockDim.x;

    if (idx < 4 * 64 * 32) {
        int kt = idx >> 11, rem = idx & 2047;
        int nt = rem >> 5, lane = rem & 31;
        int p = lane & 3, q = lane >> 2;
        int n = nt * 8 + q;
        int h = n >> 6, j = n & 63;
        int f0 = kt * 16 + p * 2;
        float c4[4];
#pragma unroll
        for (int k = 0; k < 4; ++k) {
            int f = f0 + (k >> 1) * 8 + (k & 1);
            const float* Wp = W + (h * Fd + f) * 64;
            const float* Mp = M + h * 64 * 64 + j;
            float s = 0.f;
#pragma unroll 8
            for (int u = 0; u < 64; ++u) s += __ldg(Wp + u) * __ldg(Mp + u * 64);
            c4[k] = s;
        }
        __half2 lo = __floats2half2_rn(c4[0], c4[1]);
        __half2 hi = __floats2half2_rn(c4[2], c4[3]);
        uint2 v;
        v.x = *(unsigned*)&lo;
        v.y = *(unsigned*)&hi;
        d_Cfrag[idx] = v;
    }
    if (idx < 2 * Hh * Fd) {                        // 1024 entries
        int which = idx >> 9;
        int r = idx & 511;
        int h = r >> 6, f = r & 63;
        const float* Wp = W + (h * Fd + f) * 64;
        const float* ap = a + h * 128 + which * 64;
        float s = 0.f;
#pragma unroll 8
        for (int u = 0; u < 64; ++u) s += __ldg(Wp + u) * __ldg(ap + u);
        d_wa[idx] = s;
    }

    float4 z = make_float4(0.f, 0.f, 0.f, 0.f);
    int n_oacc4 = N * Fd / 4;
    for (int i = idx; i < n_oacc4; i += nthr) ((float4*)d_oacc)[i] = z;
    int n_asum4 = N * Hh / 4;
    for (int i = idx; i < n_asum4; i += nthr) ((float4*)d_asum)[i] = z;
}

// ---------------- K1: X -> fp16 ----------------
__global__ void k_x16(const float* __restrict__ x, int total4) {
    int i = blockIdx.x * blockDim.x + threadIdx.x;
    if (i >= total4) return;
    float4 v = __ldg((const float4*)x + i);
    __half2 lo = __floats2half2_rn(v.x, v.y);
    __half2 hi = __floats2half2_rn(v.z, v.w);
    uint2 u;
    u.x = *(unsigned*)&lo;
    u.y = *(unsigned*)&hi;
    d_x16[i] = u;
}

// ---------------- K2: alpha_src/alpha_dst in fp32 ----------------
// thread t -> node n = t/16, r = t%16: which = r/8, h = r%8.
__global__ void k_alpha(const float* __restrict__ x, int N) {
    int t = blockIdx.x * blockDim.x + threadIdx.x;
    if (t >= N * 16) return;
    int n = t >> 4, r = t & 15;
    int which = r >> 3, h = r & 7;
    const float* xp = x + n * 64;
    const float* wap = d_wa + which * 512 + h * 64;
    float s = 0.f;
#pragma unroll 8
    for (int u = 0; u < 64; ++u) s += __ldg(xp + u) * wap[u];
    if (which) d_adst[n * 8 + h] = s;
    else       d_asrc[n * 8 + h] = s;
}

// ---------------- K3: g = X @ C via tensor cores (fp16 in, fp32 accum, fp16 out) ----
// Block = 256 threads / 8 warps = 64 rows x 512 cols. Warp = 16 rows x 256 cols
// (32 n8-tiles). B fragments streamed from the L1-resident 64 KB d_Cfrag table.
__global__ void __launch_bounds__(256) k_mma(int N) {
    int tid = threadIdx.x;
    int warp = tid >> 5, lane = tid & 31;
    int p = lane & 3, q = lane >> 2;
    int r0 = blockIdx.x * 64 + (warp >> 1) * 16;
    int nt0 = (warp & 1) * 32;                    // n8-tile offset (cols nt0*8)

    float acc[32][4];
#pragma unroll
    for (int t = 0; t < 32; ++t) {
        acc[t][0] = 0.f; acc[t][1] = 0.f; acc[t][2] = 0.f; acc[t][3] = 0.f;
    }

    const unsigned* xu = (const unsigned*)d_x16;  // 32 uints per row (64 halves)
    int ra = r0 + q, rb = r0 + q + 8;
    int ral = min(ra, N - 1), rbl = min(rb, N - 1);

#pragma unroll
    for (int kt = 0; kt < 4; ++kt) {
        unsigned a0 = __ldg(xu + ral * 32 + kt * 8 + p);
        unsigned a1 = __ldg(xu + rbl * 32 + kt * 8 + p);
        unsigned a2 = __ldg(xu + ral * 32 + kt * 8 + p + 4);
        unsigned a3 = __ldg(xu + rbl * 32 + kt * 8 + p + 4);
        const uint2* bf = d_Cfrag + (kt * 64 + nt0) * 32 + lane;
#pragma unroll
        for (int nt = 0; nt < 32; ++nt) {
            uint2 b = __ldg(bf + nt * 32);
            mma16816(acc[nt], a0, a1, a2, a3, b.x, b.y);
        }
    }

    unsigned* g = (unsigned*)d_g;                 // half2 units, 256 per row
#pragma unroll
    for (int nt = 0; nt < 32; ++nt) {
        int col2 = (nt0 + nt) * 4 + p;            // half2 index in row
        if (ra < N) {
            __half2 h01 = __floats2half2_rn(acc[nt][0], acc[nt][1]);
            g[(size_t)ra * 256 + col2] = *(unsigned*)&h01;
        }
        if (rb < N) {
            __half2 h23 = __floats2half2_rn(acc[nt][2], acc[nt][3]);
            g[(size_t)rb * 256 + col2] = *(unsigned*)&h23;
        }
    }
}

// ---------------- K4: attention segment sums (no weight store) ----------------
// Warp covers 4 consecutive edges x 8 heads; sorted src => segmented shfl
// pre-reduction, only run-heads issue atomicAdd.
__global__ void k_att(const int* __restrict__ edges, int E) {
    int gw = (blockIdx.x * blockDim.x + threadIdx.x) >> 5;
    int lane = threadIdx.x & 31;
    int i = lane >> 3, h = lane & 7;
    int e = gw * 4 + i;
    bool valid = e < E;

    int2 ed = make_int2(-1 - i, 0);               // distinct sentinels, never merge
    float att = 0.f;
    if (valid) {
        ed = __ldg((const int2*)edges + e);
        float s = __ldg(d_asrc + ed.x * 8 + h) + __ldg(d_adst + ed.y * 8 + h);
        s = s >= 0.f ? s : 0.2f * s;
        s = fminf(2.f, fmaxf(-2.f, s));
        att = __expf(s);
    }

    unsigned full = 0xffffffffu;
    int   s1 = __shfl_down_sync(full, ed.x, 8);
    float v1 = __shfl_down_sync(full, att, 8);
    float w1 = att + ((i < 3 && s1 == ed.x) ? v1 : 0.f);
    int   s2 = __shfl_down_sync(full, ed.x, 16);
    float v2 = __shfl_down_sync(full, w1, 16);
    float w2 = w1 + ((i < 2 && s2 == ed.x) ? v2 : 0.f);

    int sp = __shfl_up_sync(full, ed.x, 8);
    bool head = (i == 0) || (sp != ed.x);
    if (valid && head) atomicAdd(&d_asum[ed.x * 8 + h], w2);
}

// ---------------- K5: edge aggregation, uint2 g loads, inline att recompute --------
// Warp: CHUNK consecutive edges, 2 at a time. Lane layout per hh in 0..3:
// lanes 0-15 -> head 2hh cols lane*4..+3; lanes 16-31 -> head 2hh+1 cols (lane-16)*4.
// acc[4] = 4 cols at (lane&15)*4; half-warps merged by shfl at flush.
__global__ void k_edge(const int* __restrict__ edges, int E) {
    int gw = (blockIdx.x * blockDim.x + threadIdx.x) >> 5;
    int lane = threadIdx.x & 31;
    int e0 = gw * CHUNK;
    if (e0 >= E) return;
    int e1 = min(e0 + CHUNK, E);

    const uint2* __restrict__ gb = (const uint2*)d_g;     // 128 uint2 per row
    float acc[4] = {0.f, 0.f, 0.f, 0.f};
    float rs = 0.f, asrcv = 0.f;
    int cur = -1;
    unsigned full = 0xffffffffu;

    for (int e = e0; e < e1; e += 2) {
        bool hasB = (e + 1 < e1);
        int2 edA = __ldg((const int2*)edges + e);
        int2 edB = hasB ? __ldg((const int2*)edges + (e + 1)) : edA;
        float adA = (lane < 8) ? __ldg(d_adst + edA.y * 8 + lane) : 0.f;
        float adB = (lane < 8) ? __ldg(d_adst + edB.y * 8 + lane) : 0.f;

        const uint2* gpA = gb + (size_t)edA.y * 128;
        const uint2* gpB = gb + (size_t)edB.y * 128;
        uint2 gvA[4], gvB[4];
#pragma unroll
        for (int hh = 0; hh < 4; ++hh) gvA[hh] = __ldg(gpA + hh * 32 + lane);
#pragma unroll
        for (int hh = 0; hh < 4; ++hh) gvB[hh] = __ldg(gpB + hh * 32 + lane);

        // ---- edge A ----
        if (edA.x != cur) {                        // warp-uniform
            if (cur >= 0) {
#pragma unroll
                for (int k = 0; k < 4; ++k)
                    acc[k] += __shfl_down_sync(full, acc[k], 16);
                if (lane < 16) {
#pragma unroll
                    for (int k = 0; k < 4; ++k)
                        atomicAdd(&d_oacc[(size_t)cur * 64 + lane * 4 + k], acc[k]);
                }
#pragma unroll
                for (int k = 0; k < 4; ++k) acc[k] = 0.f;
            }
            cur = edA.x;
            if (lane < 8) {
                asrcv = __ldg(d_asrc + cur * 8 + lane);
                rs = 1.f / __ldg(d_asum + cur * 8 + lane);
            }
        }
        float wA = 0.f;
        if (lane < 8) {
            float s = asrcv + adA;
            s = s >= 0.f ? s : 0.2f * s;
            s = fminf(2.f, fmaxf(-2.f, s));
            wA = __expf(s) * rs;
        }
#pragma unroll
        for (int hh = 0; hh < 4; ++hh) {
            float wh = __shfl_sync(full, wA, 2 * hh + (lane >> 4));
            float2 f01 = __half22float2(*(__half2*)&gvA[hh].x);
            float2 f23 = __half22float2(*(__half2*)&gvA[hh].y);
            acc[0] += wh * f01.x; acc[1] += wh * f01.y;
            acc[2] += wh * f23.x; acc[3] += wh * f23.y;
        }

        // ---- edge B ----
        if (hasB) {
            if (edB.x != cur) {
                if (cur >= 0) {
#pragma unroll
                    for (int k = 0; k < 4; ++k)
                        acc[k] += __shfl_down_sync(full, acc[k], 16);
                    if (lane < 16) {
#pragma unroll
                        for (int k = 0; k < 4; ++k)
                            atomicAdd(&d_oacc[(size_t)cur * 64 + lane * 4 + k], acc[k]);
                    }
#pragma unroll
                    for (int k = 0; k < 4; ++k) acc[k] = 0.f;
                }
                cur = edB.x;
                if (lane < 8) {
                    asrcv = __ldg(d_asrc + cur * 8 + lane);
                    rs = 1.f / __ldg(d_asum + cur * 8 + lane);
                }
            }
            float wB = 0.f;
            if (lane < 8) {
                float s = asrcv + adB;
                s = s >= 0.f ? s : 0.2f * s;
                s = fminf(2.f, fmaxf(-2.f, s));
                wB = __expf(s) * rs;
            }
#pragma unroll
            for (int hh = 0; hh < 4; ++hh) {
                float wh = __shfl_sync(full, wB, 2 * hh + (lane >> 4));
                float2 f01 = __half22float2(*(__half2*)&gvB[hh].x);
                float2 f23 = __half22float2(*(__half2*)&gvB[hh].y);
                acc[0] += wh * f01.x; acc[1] += wh * f01.y;
                acc[2] += wh * f23.x; acc[3] += wh * f23.y;
            }
        }
    }
    if (cur >= 0) {
#pragma unroll
        for (int k = 0; k < 4; ++k)
            acc[k] += __shfl_down_sync(full, acc[k], 16);
        if (lane < 16) {
#pragma unroll
            for (int k = 0; k < 4; ++k)
                atomicAdd(&d_oacc[(size_t)cur * 64 + lane * 4 + k], acc[k]);
        }
    }
}

// ---------------- K6: final leaky ----------------
__global__ void k_final(float* __restrict__ out, int total) {
    int i = blockIdx.x * blockDim.x + threadIdx.x;
    if (i < total) out[i] = leaky(d_oacc[i]);
}

// ---------------- launch ----------------
extern "C" void kernel_launch(void* const* d_in, const int* in_sizes, int n_in,
                              void* d_out, int out_size) {
    const float* x     = (const float*)d_in[0];
    const int*   edges = (const int*)  d_in[1];
    const float* W     = (const float*)d_in[2];
    const float* a     = (const float*)d_in[3];
    const float* M     = (const float*)d_in[4];
    float* out = (float*)d_out;

    int N = in_sizes[0] / Fd;
    int E = in_sizes[1] / 2;

    k_prep<<<256, 256>>>(W, a, M, N);                                  // #1
    k_x16<<<(N * 16 + 255) / 256, 256>>>(x, N * 16);                   // #2
    k_alpha<<<(N * 16 + 255) / 256, 256>>>(x, N);                      // #3
    k_mma<<<(N + 63) / 64, 256>>>(N);                                  // #4 (ncu sample)
    k_att<<<((E + 3) / 4 * 32 + 255) / 256, 256>>>(edges, E);          // #5
    int nwarps = (E + CHUNK - 1) / CHUNK;
    k_edge<<<(nwarps * 32 + 255) / 256, 256>>>(edges, E);              // #6
    k_final<<<(N * Fd + 255) / 256, 256>>>(out, N * Fd);               // #7
}

// round 10
// speedup vs baseline: 1.3798x; 1.3798x over previous
#include <cuda_runtime.h>
#include <cuda_fp16.h>

// Problem constants (fixed by setup_inputs): N=50000, E=800000, F=64, U=64, H=8
#define Fd   64
#define Hh   8
#define HU   512          // H * U
#define NMAX 50000
#define EMAX 800000
#define CHUNK 64          // edges per warp in k_edge

// ---------------- static scratch (no allocations allowed) ----------------
__device__ __align__(16) __half d_g[(size_t)NMAX * HU];   // g fp16 (~51 MB)
__device__ __align__(16) uint2  d_x16[(size_t)NMAX * 16]; // X in fp16 (4 halves per uint2)
__device__ __align__(16) uint2  d_Cfrag[4 * 64 * 32];     // B fragments, 64 KB (kt, nt, lane)
__device__ float d_asrc[NMAX * Hh];
__device__ float d_adst[NMAX * Hh];
__device__ __align__(16) float d_asum[NMAX * Hh];         // per (src,h) attention sums
__device__ __align__(16) float d_oacc[(size_t)NMAX * Fd]; // pre-leaky output accumulator
__device__ float d_wa[2 * Hh * Fd];                       // folded attention vectors

__device__ __forceinline__ float leaky(float v) { return v >= 0.f ? v : 0.2f * v; }

__device__ __forceinline__ void mma16816(float* c, unsigned a0, unsigned a1,
                                         unsigned a2, unsigned a3,
                                         unsigned b0, unsigned b1) {
    asm volatile(
        "mma.sync.aligned.m16n8k16.row.col.f32.f16.f16.f32 "
        "{%0,%1,%2,%3}, {%4,%5,%6,%7}, {%8,%9}, {%0,%1,%2,%3};\n"
        : "+f"(c[0]), "+f"(c[1]), "+f"(c[2]), "+f"(c[3])
        : "r"(a0), "r"(a1), "r"(a2), "r"(a3), "r"(b0), "r"(b1));
}

// ---------------- K0: fold weights into B-fragments + wa; x->fp16; zero accums -----
__global__ void k_prep(const float* __restrict__ W, const float* __restrict__ a,
                       const float* __restrict__ M, const float* __restrict__ x, int N) {
    int idx = blockIdx.x * blockDim.x + threadIdx.x;
    int nthr = gridDim.x * blockDim.x;

    if (idx < 4 * 64 * 32) {
        int kt = idx >> 11, rem = idx & 2047;
        int nt = rem >> 5, lane = rem & 31;
        int p = lane & 3, q = lane >> 2;
        int n = nt * 8 + q;
        int h = n >> 6, j = n & 63;
        int f0 = kt * 16 + p * 2;
        float c4[4];
#pragma unroll
        for (int k = 0; k < 4; ++k) {
            int f = f0 + (k >> 1) * 8 + (k & 1);
            const float* Wp = W + (h * Fd + f) * 64;
            const float* Mp = M + h * 64 * 64 + j;
            float s = 0.f;
#pragma unroll 8
            for (int u = 0; u < 64; ++u) s += __ldg(Wp + u) * __ldg(Mp + u * 64);
            c4[k] = s;
        }
        __half2 lo = __floats2half2_rn(c4[0], c4[1]);
        __half2 hi = __floats2half2_rn(c4[2], c4[3]);
        uint2 v;
        v.x = *(unsigned*)&lo;
        v.y = *(unsigned*)&hi;
        d_Cfrag[idx] = v;
    }
    if (idx < 2 * Hh * Fd) {                        // 1024 entries
        int which = idx >> 9;
        int r = idx & 511;
        int h = r >> 6, f = r & 63;
        const float* Wp = W + (h * Fd + f) * 64;
        const float* ap = a + h * 128 + which * 64;
        float s = 0.f;
#pragma unroll 8
        for (int u = 0; u < 64; ++u) s += __ldg(Wp + u) * __ldg(ap + u);
        d_wa[idx] = s;
    }

    // x -> fp16 (grid-strided)
    int total4 = N * 16;
    for (int i = idx; i < total4; i += nthr) {
        float4 v = __ldg((const float4*)x + i);
        __half2 lo = __floats2half2_rn(v.x, v.y);
        __half2 hi = __floats2half2_rn(v.z, v.w);
        uint2 u;
        u.x = *(unsigned*)&lo;
        u.y = *(unsigned*)&hi;
        d_x16[i] = u;
    }

    // zero accumulators
    float4 z = make_float4(0.f, 0.f, 0.f, 0.f);
    int n_oacc4 = N * Fd / 4;
    for (int i = idx; i < n_oacc4; i += nthr) ((float4*)d_oacc)[i] = z;
    int n_asum4 = N * Hh / 4;
    for (int i = idx; i < n_asum4; i += nthr) ((float4*)d_asum)[i] = z;
}

// ---------------- K1: alpha_src/alpha_dst, smem-tiled (conflict-free) --------------
// Block = 256 threads = 16 nodes x 16 outputs (which*8+h). x rows + wa staged in
// smem with 65-float row pitch so the 16 distinct wa rows hit 16 distinct banks.
__global__ void __launch_bounds__(256) k_alpha(const float* __restrict__ x, int N) {
    __shared__ float sx[16][65];
    __shared__ float swa[16][65];
    int tid = threadIdx.x;
    int n0 = blockIdx.x * 16;

    for (int i = tid; i < 1024; i += 256) swa[i >> 6][i & 63] = d_wa[i];
    for (int i = tid; i < 1024; i += 256) {
        int row = i >> 6, col = i & 63;
        sx[row][col] = (n0 + row < N) ? __ldg(x + (size_t)(n0 + row) * 64 + col) : 0.f;
    }
    __syncthreads();

    int ln = tid >> 4;          // local node 0..15
    int r  = tid & 15;          // which*8 + h
    float s = 0.f;
#pragma unroll
    for (int u = 0; u < 64; ++u) s += sx[ln][u] * swa[r][u];

    int n = n0 + ln;
    if (n < N) {
        int which = r >> 3, h = r & 7;
        if (which) d_adst[n * 8 + h] = s;
        else       d_asrc[n * 8 + h] = s;
    }
}

// ---------------- K2: g = X @ C via tensor cores (fp16 in, fp32 accum, fp16 out) ----
__global__ void __launch_bounds__(256) k_mma(int N) {
    int tid = threadIdx.x;
    int warp = tid >> 5, lane = tid & 31;
    int p = lane & 3, q = lane >> 2;
    int r0 = blockIdx.x * 64 + (warp >> 1) * 16;
    int nt0 = (warp & 1) * 32;                    // n8-tile offset (cols nt0*8)

    float acc[32][4];
#pragma unroll
    for (int t = 0; t < 32; ++t) {
        acc[t][0] = 0.f; acc[t][1] = 0.f; acc[t][2] = 0.f; acc[t][3] = 0.f;
    }

    const unsigned* xu = (const unsigned*)d_x16;  // 32 uints per row (64 halves)
    int ra = r0 + q, rb = r0 + q + 8;
    int ral = min(ra, N - 1), rbl = min(rb, N - 1);

#pragma unroll
    for (int kt = 0; kt < 4; ++kt) {
        unsigned a0 = __ldg(xu + ral * 32 + kt * 8 + p);
        unsigned a1 = __ldg(xu + rbl * 32 + kt * 8 + p);
        unsigned a2 = __ldg(xu + ral * 32 + kt * 8 + p + 4);
        unsigned a3 = __ldg(xu + rbl * 32 + kt * 8 + p + 4);
        const uint2* bf = d_Cfrag + (kt * 64 + nt0) * 32 + lane;
#pragma unroll
        for (int nt = 0; nt < 32; ++nt) {
            uint2 b = __ldg(bf + nt * 32);
            mma16816(acc[nt], a0, a1, a2, a3, b.x, b.y);
        }
    }

    unsigned* g = (unsigned*)d_g;                 // half2 units, 256 per row
#pragma unroll
    for (int nt = 0; nt < 32; ++nt) {
        int col2 = (nt0 + nt) * 4 + p;            // half2 index in row
        if (ra < N) {
            __half2 h01 = __floats2half2_rn(acc[nt][0], acc[nt][1]);
            g[(size_t)ra * 256 + col2] = *(unsigned*)&h01;
        }
        if (rb < N) {
            __half2 h23 = __floats2half2_rn(acc[nt][2], acc[nt][3]);
            g[(size_t)rb * 256 + col2] = *(unsigned*)&h23;
        }
    }
}

// ---------------- K3: attention segment sums ----------------
// Warp covers 4 consecutive edges x 8 heads; sorted src => segmented shfl
// pre-reduction, only run-heads issue atomicAdd.
__global__ void k_att(const int* __restrict__ edges, int E) {
    int gw = (blockIdx.x * blockDim.x + threadIdx.x) >> 5;
    int lane = threadIdx.x & 31;
    int i = lane >> 3, h = lane & 7;
    int e = gw * 4 + i;
    bool valid = e < E;

    int2 ed = make_int2(-1 - i, 0);               // distinct sentinels, never merge
    float att = 0.f;
    if (valid) {
        ed = __ldg((const int2*)edges + e);
        float s = __ldg(d_asrc + ed.x * 8 + h) + __ldg(d_adst + ed.y * 8 + h);
        s = s >= 0.f ? s : 0.2f * s;
        s = fminf(2.f, fmaxf(-2.f, s));
        att = __expf(s);
    }

    unsigned full = 0xffffffffu;
    int   s1 = __shfl_down_sync(full, ed.x, 8);
    float v1 = __shfl_down_sync(full, att, 8);
    float w1 = att + ((i < 3 && s1 == ed.x) ? v1 : 0.f);
    int   s2 = __shfl_down_sync(full, ed.x, 16);
    float v2 = __shfl_down_sync(full, w1, 16);
    float w2 = w1 + ((i < 2 && s2 == ed.x) ? v2 : 0.f);

    int sp = __shfl_up_sync(full, ed.x, 8);
    bool head = (i == 0) || (sp != ed.x);
    if (valid && head) atomicAdd(&d_asum[ed.x * 8 + h], w2);
}

// ---------------- K4: edge aggregation, uint2 g loads, inline att recompute --------
__global__ void k_edge(const int* __restrict__ edges, int E) {
    int gw = (blockIdx.x * blockDim.x + threadIdx.x) >> 5;
    int lane = threadIdx.x & 31;
    int e0 = gw * CHUNK;
    if (e0 >= E) return;
    int e1 = min(e0 + CHUNK, E);

    const uint2* __restrict__ gb = (const uint2*)d_g;     // 128 uint2 per row
    float acc[4] = {0.f, 0.f, 0.f, 0.f};
    float rs = 0.f, asrcv = 0.f;
    int cur = -1;
    unsigned full = 0xffffffffu;

    for (int e = e0; e < e1; e += 2) {
        bool hasB = (e + 1 < e1);
        int2 edA = __ldg((const int2*)edges + e);
        int2 edB = hasB ? __ldg((const int2*)edges + (e + 1)) : edA;
        float adA = (lane < 8) ? __ldg(d_adst + edA.y * 8 + lane) : 0.f;
        float adB = (lane < 8) ? __ldg(d_adst + edB.y * 8 + lane) : 0.f;

        const uint2* gpA = gb + (size_t)edA.y * 128;
        const uint2* gpB = gb + (size_t)edB.y * 128;
        uint2 gvA[4], gvB[4];
#pragma unroll
        for (int hh = 0; hh < 4; ++hh) gvA[hh] = __ldg(gpA + hh * 32 + lane);
#pragma unroll
        for (int hh = 0; hh < 4; ++hh) gvB[hh] = __ldg(gpB + hh * 32 + lane);

        // ---- edge A ----
        if (edA.x != cur) {                        // warp-uniform
            if (cur >= 0) {
#pragma unroll
                for (int k = 0; k < 4; ++k)
                    acc[k] += __shfl_down_sync(full, acc[k], 16);
                if (lane < 16) {
#pragma unroll
                    for (int k = 0; k < 4; ++k)
                        atomicAdd(&d_oacc[(size_t)cur * 64 + lane * 4 + k], acc[k]);
                }
#pragma unroll
                for (int k = 0; k < 4; ++k) acc[k] = 0.f;
            }
            cur = edA.x;
            if (lane < 8) {
                asrcv = __ldg(d_asrc + cur * 8 + lane);
                rs = 1.f / __ldg(d_asum + cur * 8 + lane);
            }
        }
        float wA = 0.f;
        if (lane < 8) {
            float s = asrcv + adA;
            s = s >= 0.f ? s : 0.2f * s;
            s = fminf(2.f, fmaxf(-2.f, s));
            wA = __expf(s) * rs;
        }
#pragma unroll
        for (int hh = 0; hh < 4; ++hh) {
            float wh = __shfl_sync(full, wA, 2 * hh + (lane >> 4));
            float2 f01 = __half22float2(*(__half2*)&gvA[hh].x);
            float2 f23 = __half22float2(*(__half2*)&gvA[hh].y);
            acc[0] += wh * f01.x; acc[1] += wh * f01.y;
            acc[2] += wh * f23.x; acc[3] += wh * f23.y;
        }

        // ---- edge B ----
        if (hasB) {
            if (edB.x != cur) {
                if (cur >= 0) {
#pragma unroll
                    for (int k = 0; k < 4; ++k)
                        acc[k] += __shfl_down_sync(full, acc[k], 16);
                    if (lane < 16) {
#pragma unroll
                        for (int k = 0; k < 4; ++k)
                            atomicAdd(&d_oacc[(size_t)cur * 64 + lane * 4 + k], acc[k]);
                    }
#pragma unroll
                    for (int k = 0; k < 4; ++k) acc[k] = 0.f;
                }
                cur = edB.x;
                if (lane < 8) {
                    asrcv = __ldg(d_asrc + cur * 8 + lane);
                    rs = 1.f / __ldg(d_asum + cur * 8 + lane);
                }
            }
            float wB = 0.f;
            if (lane < 8) {
                float s = asrcv + adB;
                s = s >= 0.f ? s : 0.2f * s;
                s = fminf(2.f, fmaxf(-2.f, s));
                wB = __expf(s) * rs;
            }
#pragma unroll
            for (int hh = 0; hh < 4; ++hh) {
                float wh = __shfl_sync(full, wB, 2 * hh + (lane >> 4));
                float2 f01 = __half22float2(*(__half2*)&gvB[hh].x);
                float2 f23 = __half22float2(*(__half2*)&gvB[hh].y);
                acc[0] += wh * f01.x; acc[1] += wh * f01.y;
                acc[2] += wh * f23.x; acc[3] += wh * f23.y;
            }
        }
    }
    if (cur >= 0) {
#pragma unroll
        for (int k = 0; k < 4; ++k)
            acc[k] += __shfl_down_sync(full, acc[k], 16);
        if (lane < 16) {
#pragma unroll
            for (int k = 0; k < 4; ++k)
                atomicAdd(&d_oacc[(size_t)cur * 64 + lane * 4 + k], acc[k]);
        }
    }
}

// ---------------- K5: final leaky ----------------
__global__ void k_final(float* __restrict__ out, int total) {
    int i = blockIdx.x * blockDim.x + threadIdx.x;
    if (i < total) out[i] = leaky(d_oacc[i]);
}

// ---------------- launch ----------------
extern "C" void kernel_launch(void* const* d_in, const int* in_sizes, int n_in,
                              void* d_out, int out_size) {
    const float* x     = (const float*)d_in[0];
    const int*   edges = (const int*)  d_in[1];
    const float* W     = (const float*)d_in[2];
    const float* a     = (const float*)d_in[3];
    const float* M     = (const float*)d_in[4];
    float* out = (float*)d_out;

    int N = in_sizes[0] / Fd;
    int E = in_sizes[1] / 2;

    k_prep<<<256, 256>>>(W, a, M, x, N);                               // #1
    k_alpha<<<(N + 15) / 16, 256>>>(x, N);                             // #2
    k_mma<<<(N + 63) / 64, 256>>>(N);                                  // #3
    k_att<<<((E + 3) / 4 * 32 + 255) / 256, 256>>>(edges, E);          // #4 (ncu sample)
    int nwarps = (E + CHUNK - 1) / CHUNK;
    k_edge<<<(nwarps * 32 + 255) / 256, 256>>>(edges, E);              // #5
    k_final<<<(N * Fd + 255) / 256, 256>>>(out, N * Fd);               // #6
}